// round 6
// baseline (speedup 1.0000x reference)
#include <cuda_runtime.h>
#include <cuda_fp16.h>
#include <math.h>
#include <stdint.h>

#define N_NODES   100000
#define N_EDGES   3200000
#define NE_TOT    (N_EDGES + N_NODES)   // edges + self loops
#define IN_C      256
#define OUT_C     64
#define NEG_SLOPE 0.2f

#define SCAN_BS   1024
#define SCAN_NB   ((N_NODES + SCAN_BS - 1) / SCAN_BS)   // 98

#define GEMM_BLOCKS  782                 // ceil(100000 / 128)
#define HIST_BLOCKS  1568
#define FUSED_BLOCKS (GEMM_BLOCKS + HIST_BLOCKS)

// ---------------- scratch (static device globals; no allocation) ----------------
__device__ __half2 g_hh[(size_t)N_NODES * 32];    // 12.8 MB: h in fp16 (32 half2/row)
__device__ float   g_si[N_NODES];                 // h @ a_i
__device__ float   g_sj[N_NODES];                 // h @ a_j
__device__ int     g_cnt[N_NODES];                // histogram by col
__device__ int     g_start[N_NODES + 1];          // CSR offsets
__device__ int     g_cur[N_NODES];                // placement cursors
__device__ int     g_bsum[SCAN_NB];               // block sums for scan
__device__ float2  g_csr[NE_TOT];                 // {row (bitcast), p = exp(e)}

// ---------------- helpers ----------------
__device__ __forceinline__ void split2(float e, float o, uint32_t& hi, uint32_t& lo) {
    asm("cvt.rn.bf16x2.f32 %0, %1, %2;" : "=r"(hi) : "f"(o), "f"(e));
    float fe = __uint_as_float(hi << 16);
    float fo = __uint_as_float(hi & 0xffff0000u);
    asm("cvt.rn.bf16x2.f32 %0, %1, %2;" : "=r"(lo) : "f"(o - fo), "f"(e - fe));
}

__device__ __forceinline__ void mma_bf16(float* d, const uint32_t* a,
                                         uint32_t b0, uint32_t b1) {
    asm volatile(
        "mma.sync.aligned.m16n8k16.row.col.f32.bf16.bf16.f32 "
        "{%0,%1,%2,%3}, {%4,%5,%6,%7}, {%8,%9}, {%0,%1,%2,%3};"
        : "+f"(d[0]), "+f"(d[1]), "+f"(d[2]), "+f"(d[3])
        : "r"(a[0]), "r"(a[1]), "r"(a[2]), "r"(a[3]), "r"(b0), "r"(b1));
}

// ---------------- kernel: init (self-loop pre-counted in histogram) ----------------
__global__ void zero_kernel() {
    int i = blockIdx.x * blockDim.x + threadIdx.x;
    if (i < N_NODES) g_cnt[i] = 1;
}

// ---------------- fused kernel: bf16-split TC GEMM + scores | histogram ----------
__global__ __launch_bounds__(256) void gemm_hist_kernel(const float* __restrict__ x,
                                                        const float* __restrict__ W,
                                                        const float* __restrict__ a,
                                                        const int* __restrict__ ei) {
    __shared__ uint32_t Bhi[64 * 68];
    __shared__ uint32_t Blo[64 * 68];
    __shared__ float sa[2 * OUT_C];

    const int tid = threadIdx.x;

    if (blockIdx.x >= GEMM_BLOCKS) {
        // ---- histogram role ----
        int i = (blockIdx.x - GEMM_BLOCKS) * 256 + tid;
        const int stride = HIST_BLOCKS * 256;
        const int* col = ei + N_EDGES;
        for (; i < N_EDGES; i += stride)
            atomicAdd(&g_cnt[col[i]], 1);
        return;
    }

    // ---- GEMM role ----
    const int warp = tid >> 5;
    const int lane = tid & 31;
    const int qrow = lane >> 2;
    const int qcol = lane & 3;

    if (tid < 2 * OUT_C) sa[tid] = a[tid];

    const int row0 = blockIdx.x * 128 + warp * 16 + qrow;
    const int row1 = row0 + 8;
    const bool v0 = row0 < N_NODES;
    const bool v1 = row1 < N_NODES;
    const float* xr0 = x + (size_t)(v0 ? row0 : 0) * IN_C;
    const float* xr1 = x + (size_t)(v1 ? row1 : 0) * IN_C;

    float C[8][4];
#pragma unroll
    for (int nt = 0; nt < 8; nt++)
#pragma unroll
        for (int j = 0; j < 4; j++) C[nt][j] = 0.0f;

    for (int chunk = 0; chunk < 2; chunk++) {
        const int kbase = chunk * 128;
        __syncthreads();
        for (int w = tid; w < 64 * 64; w += 256) {
            int n  = w >> 6;
            int kw = w & 63;
            float2 v = *(const float2*)(W + (size_t)n * IN_C + kbase + kw * 2);
            uint32_t hi, lo;
            split2(v.x, v.y, hi, lo);
            Bhi[n * 68 + kw] = hi;
            Blo[n * 68 + kw] = lo;
        }
        __syncthreads();

#pragma unroll
        for (int s = 0; s < 8; s++) {
            const int k0 = kbase + s * 16;
            float2 a00 = *(const float2*)(xr0 + k0 + 2 * qcol);
            float2 a10 = *(const float2*)(xr1 + k0 + 2 * qcol);
            float2 a01 = *(const float2*)(xr0 + k0 + 8 + 2 * qcol);
            float2 a11 = *(const float2*)(xr1 + k0 + 8 + 2 * qcol);
            uint32_t ahi[4], alo[4];
            split2(a00.x, a00.y, ahi[0], alo[0]);
            split2(a10.x, a10.y, ahi[1], alo[1]);
            split2(a01.x, a01.y, ahi[2], alo[2]);
            split2(a11.x, a11.y, ahi[3], alo[3]);

            const int bb = qrow * 68 + s * 8 + qcol;
#pragma unroll
            for (int nt = 0; nt < 8; nt++) {
                const int nb = nt * 8 * 68 + bb;
                uint32_t bh0 = Bhi[nb], bh1 = Bhi[nb + 4];
                uint32_t bl0 = Blo[nb], bl1 = Blo[nb + 4];
                mma_bf16(C[nt], ahi, bh0, bh1);
                mma_bf16(C[nt], ahi, bl0, bl1);
                mma_bf16(C[nt], alo, bh0, bh1);
            }
        }
    }

    // epilogue: store h (fp16), fused attention scores (fp32)
    float si0 = 0.f, sj0 = 0.f, si1 = 0.f, sj1 = 0.f;
#pragma unroll
    for (int nt = 0; nt < 8; nt++) {
        int col = nt * 8 + 2 * qcol;
        int cw  = nt * 4 + qcol;        // half2 index within row
        if (v0) g_hh[((size_t)row0 << 5) + cw] = __floats2half2_rn(C[nt][0], C[nt][1]);
        if (v1) g_hh[((size_t)row1 << 5) + cw] = __floats2half2_rn(C[nt][2], C[nt][3]);
        si0 += C[nt][0] * sa[col]          + C[nt][1] * sa[col + 1];
        sj0 += C[nt][0] * sa[OUT_C + col]  + C[nt][1] * sa[OUT_C + col + 1];
        si1 += C[nt][2] * sa[col]          + C[nt][3] * sa[col + 1];
        sj1 += C[nt][2] * sa[OUT_C + col]  + C[nt][3] * sa[OUT_C + col + 1];
    }
#pragma unroll
    for (int off = 1; off < 4; off <<= 1) {
        si0 += __shfl_xor_sync(0xffffffffu, si0, off);
        sj0 += __shfl_xor_sync(0xffffffffu, sj0, off);
        si1 += __shfl_xor_sync(0xffffffffu, si1, off);
        sj1 += __shfl_xor_sync(0xffffffffu, sj1, off);
    }
    if (qcol == 0) {
        if (v0) { g_si[row0] = si0; g_sj[row0] = sj0; }
        if (v1) { g_si[row1] = si1; g_sj[row1] = sj1; }
    }
}

// ---------------- scan1: warp-shfl block scan ----------------
__global__ __launch_bounds__(SCAN_BS) void scan1_kernel() {
    __shared__ int wsum[32];
    const int tid  = threadIdx.x;
    const int lane = tid & 31;
    const int wid  = tid >> 5;
    const int i    = blockIdx.x * SCAN_BS + tid;

    int v = (i < N_NODES) ? g_cnt[i] : 0;
    int incl = v;
#pragma unroll
    for (int off = 1; off < 32; off <<= 1) {
        int t = __shfl_up_sync(0xffffffffu, incl, off);
        if (lane >= off) incl += t;
    }
    if (lane == 31) wsum[wid] = incl;
    __syncthreads();
    if (wid == 0) {
        int w = wsum[lane];
        int s = w;
#pragma unroll
        for (int off = 1; off < 32; off <<= 1) {
            int t = __shfl_up_sync(0xffffffffu, s, off);
            if (lane >= off) s += t;
        }
        wsum[lane] = s - w;   // exclusive warp offset
    }
    __syncthreads();
    int excl = incl - v + wsum[wid];
    if (i < N_NODES) g_start[i] = excl;
    if (tid == SCAN_BS - 1) g_bsum[blockIdx.x] = excl + v;
}

// ---------------- scan2: one-warp shfl scan over 98 block sums ----------------
__global__ void scan2_kernel() {
    const int lane = threadIdx.x;
    int run = 0;
#pragma unroll
    for (int g = 0; g < (SCAN_NB + 31) / 32; g++) {
        int i = g * 32 + lane;
        int v = (i < SCAN_NB) ? g_bsum[i] : 0;
        int s = v;
#pragma unroll
        for (int off = 1; off < 32; off <<= 1) {
            int t = __shfl_up_sync(0xffffffffu, s, off);
            if (lane >= off) s += t;
        }
        if (i < SCAN_NB) g_bsum[i] = run + s - v;
        run += __shfl_sync(0xffffffffu, s, 31);
    }
}

__global__ void scan3_kernel() {
    int i = blockIdx.x * blockDim.x + threadIdx.x;
    if (i < N_NODES) {
        int s = g_start[i] + g_bsum[i >> 10];
        g_start[i] = s;
        g_cur[i]   = s;
        if (i == 0) g_start[N_NODES] = NE_TOT;
    }
}

// ---------------- kernel: placement — build CSR entries {row, p} ----------------
__global__ void place_kernel(const int* __restrict__ ei) {
    int i = blockIdx.x * blockDim.x + threadIdx.x;
    if (i >= NE_TOT) return;
    int r, c;
    if (i < N_EDGES) { r = ei[i]; c = ei[N_EDGES + i]; }
    else             { r = c = i - N_EDGES; }
    float e = g_si[c] + g_sj[r];
    e = (e >= 0.f) ? e : NEG_SLOPE * e;
    float p = expf(e);                        // shift-free softmax weight; bounded
    int pos = atomicAdd(&g_cur[c], 1);
    g_csr[pos] = make_float2(__int_as_float(r), p);
}

// ---------------- kernel: warp-per-node fused softmax + aggregate (fp16 h) -------
__global__ __launch_bounds__(256) void gather_kernel(float* __restrict__ out) {
    int warp = (int)((blockIdx.x * 256 + threadIdx.x) >> 5);
    int lane = threadIdx.x & 31;
    if (warp >= N_NODES) return;

    int s = g_start[warp];
    int e = g_start[warp + 1];

    float acc0 = 0.f, acc1 = 0.f, sp = 0.f;
#pragma unroll 4
    for (int k = s; k < e; k++) {
        float2 t = g_csr[k];                  // uniform within warp
        int   r  = __float_as_int(t.x);
        float p  = t.y;
        sp += p;
        float2 h2 = __half22float2(g_hh[((size_t)r << 5) + lane]);
        acc0 = fmaf(p, h2.x, acc0);
        acc1 = fmaf(p, h2.y, acc1);
    }
    float inv = 1.0f / sp;                    // sp > 0: self-loop always present
    float2 o = make_float2(acc0 * inv, acc1 * inv);
    *(float2*)(out + ((size_t)warp << 6) + (lane << 1)) = o;
}

// ---------------- launch ----------------
extern "C" void kernel_launch(void* const* d_in, const int* in_sizes, int n_in,
                              void* d_out, int out_size) {
    const float* x  = (const float*)d_in[0];
    const int*   ei = (const int*)  d_in[1];
    const float* W  = (const float*)d_in[2];
    const float* a  = (const float*)d_in[3];
    float* out = (float*)d_out;

    zero_kernel<<<(N_NODES + 255) / 256, 256>>>();
    gemm_hist_kernel<<<FUSED_BLOCKS, 256>>>(x, W, a, ei);
    scan1_kernel<<<SCAN_NB, SCAN_BS>>>();
    scan2_kernel<<<1, 32>>>();
    scan3_kernel<<<(N_NODES + 255) / 256, 256>>>();
    place_kernel<<<(NE_TOT + 255) / 256, 256>>>(ei);
    long long gthreads = (long long)N_NODES * 32;
    gather_kernel<<<(unsigned)((gthreads + 255) / 256), 256>>>(out);
}